// round 4
// baseline (speedup 1.0000x reference)
#include <cuda_runtime.h>
#include <cuda_bf16.h>
#include <math_constants.h>

#define D       32000
#define D4      8000            // D/4 float4s
#define NROWS   4096
#define TA      256
#define NWARP   8
#define CHUNK4  1000            // float4s per warp chunk
#define SUBF4   125             // float4s per sub-step (4 per lane, predicated)
#define NSUB    8
#define WCAP    1024            // per-warp candidate capacity
#define CHI     0.005590169943749474f   // (1/32000)^0.5 (double-folded like reference)

__device__ float g_loss[NROWS];
__device__ int   g_done;        // zero-init; last block resets to 0 (graph-replay safe)

__device__ __forceinline__ float warp_sum(float v) {
    #pragma unroll
    for (int o = 16; o; o >>= 1) v += __shfl_xor_sync(0xffffffffu, v, o);
    return v;
}
__device__ __forceinline__ float warp_max(float v) {
    #pragma unroll
    for (int o = 16; o; o >>= 1) v = fmaxf(v, __shfl_xor_sync(0xffffffffu, v, o));
    return v;
}

#define FOR16(OP) OP(c0.x) OP(c0.y) OP(c0.z) OP(c0.w) \
                  OP(c1.x) OP(c1.y) OP(c1.z) OP(c1.w) \
                  OP(c2.x) OP(c2.y) OP(c2.z) OP(c2.w) \
                  OP(c3.x) OP(c3.y) OP(c3.z) OP(c3.w)

// ============================================================================
// Fused kernel: one CTA (8 warps) per row. SINGLE DRAM pass:
// register-staged streaming filter (running-max threshold, superset-safe)
// -> in-place prune with true row max -> all-warp bisection -> loss
// -> last block reduces the mean in-kernel.
// ============================================================================
__global__ void __launch_bounds__(TA) fused_kernel(const float* __restrict__ X,
                                                   const int*   __restrict__ target,
                                                   float*       __restrict__ out)
{
    __shared__ float s_buf[NWARP][WCAP];   // 32 KB candidates (Xa scale)
    __shared__ float s_part[2][NWARP];
    __shared__ float s_p3[3][NWARP];
    __shared__ float s_max[NWARP];
    __shared__ int   s_fb;
    __shared__ int   s_last;

    const int row  = blockIdx.x;
    const int tid  = threadIdx.x;
    const int lane = tid & 31;
    const int wid  = tid >> 5;

    if (tid == 0) s_fb = 0;
    __syncthreads();

    const float4* __restrict__ Xr4 = reinterpret_cast<const float4*>(X + (size_t)row * D);
    const float*  __restrict__ Xr  = X + (size_t)row * D;
    const float4* __restrict__ W4  = Xr4 + wid * CHUNK4;

    float xt = 0.f;
    if (tid == 0) xt = Xr[target[row]];

    // ---- single-pass streaming filter (per warp, register staged) ----
    float m_run = -CUDART_INF_F;
    int   k = 0;

    const float4 FILL = make_float4(-CUDART_INF_F, -CUDART_INF_F, -CUDART_INF_F, -CUDART_INF_F);
    float4 n0, n1, n2, n3;
    {   // prefetch sub 0
        int i0 = lane, i1 = lane + 32, i2 = lane + 64, i3 = lane + 96;
        n0 = (i0 < SUBF4) ? W4[i0] : FILL;
        n1 = (i1 < SUBF4) ? W4[i1] : FILL;
        n2 = (i2 < SUBF4) ? W4[i2] : FILL;
        n3 = (i3 < SUBF4) ? W4[i3] : FILL;
    }

    #pragma unroll 1
    for (int sub = 0; sub < NSUB; sub++) {
        float4 c0 = n0, c1 = n1, c2 = n2, c3 = n3;
        if (sub + 1 < NSUB) {   // prefetch next sub-chunk
            int b = (sub + 1) * SUBF4;
            int i0 = lane, i1 = lane + 32, i2 = lane + 64, i3 = lane + 96;
            n0 = (i0 < SUBF4) ? W4[b + i0] : FILL;
            n1 = (i1 < SUBF4) ? W4[b + i1] : FILL;
            n2 = (i2 < SUBF4) ? W4[b + i2] : FILL;
            n3 = (i3 < SUBF4) ? W4[b + i3] : FILL;
        }

        // sub-chunk max (includes own values -> threshold valid superset filter)
        float mx = fmaxf(fmaxf(fmaxf(c0.x, c0.y), fmaxf(c0.z, c0.w)),
                   fmaxf(fmaxf(fmaxf(c1.x, c1.y), fmaxf(c1.z, c1.w)),
                   fmaxf(fmaxf(fmaxf(c2.x, c2.y), fmaxf(c2.z, c2.w)),
                         fmaxf(fmaxf(c3.x, c3.y), fmaxf(c3.z, c3.w)))));
        m_run = fmaxf(m_run, warp_max(mx));
        const float th = m_run - 2.0f - 1e-5f;   // X-scale; <= rowmaxX-2 always

        int ks = 0;
        #define CNT(a) ks += ((a) > th);
        FOR16(CNT)
        #undef CNT

        int inc = ks;
        #pragma unroll
        for (int o = 1; o < 32; o <<= 1) {
            int n = __shfl_up_sync(0xffffffffu, inc, o);
            if (lane >= o) inc += n;
        }
        int off = k + (inc - ks);
        #define WR(a) if ((a) > th) { if (off < WCAP) s_buf[wid][off] = 0.5f * (a); off++; }
        FOR16(WR)
        #undef WR
        k += __shfl_sync(0xffffffffu, inc, 31);
    }

    if (k > WCAP) s_fb = 1;                 // benign race (all write 1)
    if (lane == 0) s_max[wid] = m_run;      // exact chunk max
    __syncthreads();

    float rmaxX = s_max[0];
    #pragma unroll
    for (int w = 1; w < NWARP; w++) rmaxX = fmaxf(rmaxX, s_max[w]);
    const float rmax = 0.5f * rmaxX;        // exact
    const bool  fb   = (s_fb != 0);

    // ---- in-place prune to true candidate set (Xa > rmax - 1, with margin) ----
    int cnt = 0;
    if (!fb) {
        const float tpa = rmax - 1.0f - 5e-6f;
        const int nb = (k + 31) >> 5;
        for (int j = 0; j < nb; j++) {
            int i = 32 * j + lane;
            float v = (i < k) ? s_buf[wid][i] : -CUDART_INF_F;
            bool pred = v > tpa;
            unsigned m = __ballot_sync(0xffffffffu, pred);   // also orders LDS before STS
            if (pred) s_buf[wid][cnt + __popc(m & ((1u << lane) - 1u))] = v;
            cnt += __popc(m);
        }
    }

    // ---- per-warp partial f(tau) ----
    auto fpart = [&](float tau) -> float {
        float acc = 0.f;
        if (!fb) {
            #pragma unroll 4
            for (int i = lane; i < cnt; i += 32) {
                float t = fmaxf(s_buf[wid][i] - tau, 0.f);
                acc = fmaf(t, t, acc);
            }
        } else {
            for (int i = tid; i < D; i += TA) {
                float t = fmaxf(0.5f * Xr[i] - tau, 0.f);
                acc = fmaf(t, t, acc);
            }
        }
        return warp_sum(acc);
    };

    float tau_lo = rmax - 1.0f;
    const float tau_hi = rmax - CHI;

    {   // f_lo computed ONCE (matches reference closure)
        float p = fpart(tau_lo);
        if (lane == 0) s_part[0][wid] = p;
    }
    __syncthreads();
    float f_lo = -1.0f;
    #pragma unroll
    for (int w = 0; w < NWARP; w++) f_lo += s_part[0][w];
    __syncthreads();

    float dm = tau_hi - tau_lo;
    float tau_m = tau_lo;
    #pragma unroll 1
    for (int it = 0; it < 50; it++) {
        dm *= 0.5f;
        tau_m = tau_lo + dm;
        float p = fpart(tau_m);
        int b = it & 1;
        if (lane == 0) s_part[b][wid] = p;
        __syncthreads();
        float f_m = -1.0f;
        #pragma unroll
        for (int w = 0; w < NWARP; w++) f_m += s_part[b][w];
        if (f_m * f_lo >= 0.f) tau_lo = tau_m;   // identical on every thread
    }

    // ---- final stats at tau_m ----
    float S = 0.f, A15 = 0.f, PX = 0.f;
    if (!fb) {
        #pragma unroll 4
        for (int i = lane; i < cnt; i += 32) {
            float v = s_buf[wid][i];
            float t = fmaxf(v - tau_m, 0.f);
            float pr = t * t;
            S += pr; A15 = fmaf(pr, t, A15); PX = fmaf(pr, v, PX);
        }
    } else {
        for (int i = tid; i < D; i += TA) {
            float v = 0.5f * Xr[i];
            float t = fmaxf(v - tau_m, 0.f);
            float pr = t * t;
            S += pr; A15 = fmaf(pr, t, A15); PX = fmaf(pr, v, PX);
        }
    }
    S = warp_sum(S); A15 = warp_sum(A15); PX = warp_sum(PX);
    if (lane == 0) { s_p3[0][wid] = S; s_p3[1][wid] = A15; s_p3[2][wid] = PX; }
    __syncthreads();

    if (tid == 0) {
        float St = 0.f, At = 0.f, Pt = 0.f;
        #pragma unroll
        for (int w = 0; w < NWARP; w++) { St += s_p3[0][w]; At += s_p3[1][w]; Pt += s_p3[2][w]; }
        float sum_p15 = At / (St * sqrtf(St));
        float omega   = (1.0f - sum_p15) / 0.75f;     // alpha*(alpha-1) = 0.75
        g_loss[row] = omega + 2.0f * Pt / St - xt;

        __threadfence();
        int t = atomicAdd(&g_done, 1);
        s_last = (t == NROWS - 1);
    }
    __syncthreads();

    // ---- last block: deterministic mean over all rows ----
    if (s_last) {
        if (tid == 0) g_done = 0;            // reset for graph replay
        __threadfence();
        float a = 0.f;
        #pragma unroll 4
        for (int i = tid; i < NROWS; i += TA) a += g_loss[i];
        a = warp_sum(a);
        if (lane == 0) s_p3[0][wid] = a;
        __syncthreads();
        if (tid == 0) {
            float tot = 0.f;
            #pragma unroll
            for (int w = 0; w < NWARP; w++) tot += s_p3[0][w];
            out[0] = tot / (float)NROWS;
        }
    }
}

// ============================================================================
extern "C" void kernel_launch(void* const* d_in, const int* in_sizes, int n_in,
                              void* d_out, int out_size)
{
    const float* X      = (const float*)d_in[0];
    const int*   target = (const int*)  d_in[1];
    float*       out    = (float*)d_out;

    fused_kernel<<<NROWS, TA>>>(X, target, out);
}

// round 5
// speedup vs baseline: 1.3952x; 1.3952x over previous
#include <cuda_runtime.h>
#include <cuda_bf16.h>
#include <math_constants.h>

#define D       32000
#define D4      8000
#define NROWS   4096
#define TA      256
#define NWARP   8
#define CHUNK4  1000            // float4s per warp chunk
#define SUBF4   125             // float4s per sub-step
#define NSUB    8
#define WCAP    832             // per-warp coarse-candidate capacity (exp 635, +8.5 sigma)
#define RC      12              // register-staged candidates per lane (384/warp)
#define NBIS    8
#define NNEWT   4
#define XT      1.0f            // coarse threshold on X scale; valid iff rowmaxX >= XT+2 (checked)
#define CHI     0.005590169943749474f   // (1/32000)^0.5

__device__ float g_loss[NROWS];
__device__ int   g_done;        // zero-init; last block resets (graph-replay safe)

__device__ __forceinline__ float warp_sum(float v) {
    #pragma unroll
    for (int o = 16; o; o >>= 1) v += __shfl_xor_sync(0xffffffffu, v, o);
    return v;
}
__device__ __forceinline__ float warp_max(float v) {
    #pragma unroll
    for (int o = 16; o; o >>= 1) v = fmaxf(v, __shfl_xor_sync(0xffffffffu, v, o));
    return v;
}

#define FOR16(OP) OP(c0.x) OP(c0.y) OP(c0.z) OP(c0.w) \
                  OP(c1.x) OP(c1.y) OP(c1.z) OP(c1.w) \
                  OP(c2.x) OP(c2.y) OP(c2.z) OP(c2.w) \
                  OP(c3.x) OP(c3.y) OP(c3.z) OP(c3.w)

__global__ void __launch_bounds__(TA, 4) fused_kernel(const float* __restrict__ X,
                                                      const int*   __restrict__ target,
                                                      float*       __restrict__ out)
{
    __shared__ float s_buf[NWARP][WCAP];     // 26.6 KB coarse candidates (Xa scale)
    __shared__ float s_F[2][NWARP], s_G[2][NWARP];
    __shared__ float s_p3[3][NWARP];
    __shared__ float s_max[NWARP];
    __shared__ int   s_fb;
    __shared__ int   s_last;

    const int row  = blockIdx.x;
    const int tid  = threadIdx.x;
    const int lane = tid & 31;
    const int wid  = tid >> 5;

    if (tid == 0) s_fb = 0;
    __syncthreads();

    const float4* __restrict__ Xr4 = reinterpret_cast<const float4*>(X + (size_t)row * D);
    const float*  __restrict__ Xr  = X + (size_t)row * D;
    const float4* __restrict__ W4  = Xr4 + wid * CHUNK4;

    float xt = 0.f;
    if (tid == 0) xt = Xr[target[row]];

    // ================= single-pass filter, constant threshold, 8 LDG.128 in flight =========
    const float4 FILL = make_float4(-CUDART_INF_F, -CUDART_INF_F, -CUDART_INF_F, -CUDART_INF_F);
    #define LOADSUB(dst0,dst1,dst2,dst3,sub) do {                        \
        int _b = (sub) * SUBF4;                                          \
        dst0 = W4[_b + lane];                                            \
        dst1 = W4[_b + lane + 32];                                       \
        dst2 = W4[_b + lane + 64];                                       \
        dst3 = (lane + 96 < SUBF4) ? W4[_b + lane + 96] : FILL;          \
    } while (0)

    float4 a0, a1, a2, a3, b0, b1, b2, b3;
    LOADSUB(a0, a1, a2, a3, 0);
    LOADSUB(b0, b1, b2, b3, 1);

    float m_run = -CUDART_INF_F;
    int   k = 0;

    #pragma unroll
    for (int sub = 0; sub < NSUB; sub++) {
        float4 c0 = a0, c1 = a1, c2 = a2, c3 = a3;
        a0 = b0; a1 = b1; a2 = b2; a3 = b3;
        if (sub + 2 < NSUB) LOADSUB(b0, b1, b2, b3, sub + 2);

        // running per-lane max over ALL values (exact row max at the end)
        #define MX(a) m_run = fmaxf(m_run, (a));
        FOR16(MX)
        #undef MX

        int ks = 0;
        #define CNT(a) ks += ((a) > XT);
        FOR16(CNT)
        #undef CNT

        int inc = ks;
        #pragma unroll
        for (int o = 1; o < 32; o <<= 1) {
            int n = __shfl_up_sync(0xffffffffu, inc, o);
            if (lane >= o) inc += n;
        }
        int off = k + (inc - ks);
        #define WR(a) if ((a) > XT) { if (off < WCAP) s_buf[wid][off] = 0.5f * (a); off++; }
        FOR16(WR)
        #undef WR
        k += __shfl_sync(0xffffffffu, inc, 31);
    }
    #undef LOADSUB

    if (k > WCAP) s_fb = 1;                 // benign race
    m_run = warp_max(m_run);
    if (lane == 0) s_max[wid] = m_run;
    __syncthreads();

    float rmaxX = s_max[0];
    #pragma unroll
    for (int w = 1; w < NWARP; w++) rmaxX = fmaxf(rmaxX, s_max[w]);
    const float rmax = 0.5f * rmaxX;        // exact
    // fallback if coarse threshold was not a valid superset filter (never for this data)
    const bool fb = (s_fb != 0) || (rmaxX - 2.0f < XT + 1e-4f);

    // ================= prune to true candidates (Xa > rmax-1), stage in registers ==========
    int cnt = 0;
    float C[RC];
    bool ext = false;
    if (!fb) {
        const float tpa = rmax - 1.0f - 5e-6f;   // margin adds only zero-contributing elems
        const int kk = (k < WCAP) ? k : WCAP;
        const int nb = (kk + 31) >> 5;
        for (int j = 0; j < nb; j++) {
            int i = 32 * j + lane;
            float v = (i < kk) ? s_buf[wid][i] : -CUDART_INF_F;
            bool pred = v > tpa;
            unsigned m = __ballot_sync(0xffffffffu, pred);   // orders LDS before STS
            if (pred) s_buf[wid][cnt + __popc(m & ((1u << lane) - 1u))] = v;
            cnt += __popc(m);
        }
        #pragma unroll
        for (int r = 0; r < RC; r++) {
            int i = lane + 32 * r;
            C[r] = (i < cnt) ? s_buf[wid][i] : -1e30f;
        }
        ext = (cnt > 32 * RC);
    } else {
        #pragma unroll
        for (int r = 0; r < RC; r++) C[r] = -1e30f;
    }

    // ================= solve: 8 bisection + 4 safeguarded Newton ============================
    const float tau_lo0 = rmax - 1.0f;
    const float tau_hi  = rmax - CHI;
    float tau_lo = tau_lo0;
    float dm = tau_hi - tau_lo;
    float tau_m = tau_lo;
    int pb = 0;

    #pragma unroll 1
    for (int it = 0; it < NBIS + NNEWT; it++) {
        const bool newton = (it >= NBIS);
        float te;
        if (!newton) { dm *= 0.5f; te = tau_lo + dm; }
        else         { te = tau_m; }

        float F = 0.f, G = 0.f;
        if (!fb) {
            #pragma unroll
            for (int r = 0; r < RC; r++) {
                float t = fmaxf(C[r] - te, 0.f);
                F = fmaf(t, t, F); G += t;
            }
            if (ext) {
                for (int i = 32 * RC + lane; i < cnt; i += 32) {
                    float t = fmaxf(s_buf[wid][i] - te, 0.f);
                    F = fmaf(t, t, F); G += t;
                }
            }
        } else {
            for (int i = tid; i < D; i += TA) {
                float t = fmaxf(0.5f * Xr[i] - te, 0.f);
                F = fmaf(t, t, F); G += t;
            }
        }
        #pragma unroll
        for (int o = 16; o; o >>= 1) {
            F += __shfl_xor_sync(0xffffffffu, F, o);
            G += __shfl_xor_sync(0xffffffffu, G, o);
        }
        if (lane == 0) { s_F[pb][wid] = F; s_G[pb][wid] = G; }
        __syncthreads();
        float Ft = 0.f, Gt = 0.f;
        #pragma unroll
        for (int w = 0; w < NWARP; w++) { Ft += s_F[pb][w]; Gt += s_G[pb][w]; }
        const float f = Ft - 1.0f;

        if (!newton) {
            if (f >= 0.f) tau_lo = te;       // f(tau_lo)>=0 invariant (f_lo>=0 provably)
            if (it == NBIS - 1) tau_m = tau_lo;
        } else {
            float tn = te + f / (2.0f * Gt); // f'(tau) = -2*Sum t ; Gt >= CHI > 0
            tau_m = fminf(fmaxf(tn, tau_lo0), tau_hi);
        }
        pb ^= 1;
    }

    // ================= final stats at tau_m =================================================
    float S = 0.f, A15 = 0.f, PX = 0.f;
    if (!fb) {
        #pragma unroll
        for (int r = 0; r < RC; r++) {
            float v = C[r];
            float t = fmaxf(v - tau_m, 0.f);
            float pr = t * t;
            S += pr; A15 = fmaf(pr, t, A15); PX = fmaf(pr, fmaxf(v, 0.f) + fminf(v, 0.f), PX);
        }
        if (ext) {
            for (int i = 32 * RC + lane; i < cnt; i += 32) {
                float v = s_buf[wid][i];
                float t = fmaxf(v - tau_m, 0.f);
                float pr = t * t;
                S += pr; A15 = fmaf(pr, t, A15); PX = fmaf(pr, v, PX);
            }
        }
    } else {
        for (int i = tid; i < D; i += TA) {
            float v = 0.5f * Xr[i];
            float t = fmaxf(v - tau_m, 0.f);
            float pr = t * t;
            S += pr; A15 = fmaf(pr, t, A15); PX = fmaf(pr, v, PX);
        }
    }
    S = warp_sum(S); A15 = warp_sum(A15); PX = warp_sum(PX);
    if (lane == 0) { s_p3[0][wid] = S; s_p3[1][wid] = A15; s_p3[2][wid] = PX; }
    __syncthreads();

    if (tid == 0) {
        float St = 0.f, At = 0.f, Pt = 0.f;
        #pragma unroll
        for (int w = 0; w < NWARP; w++) { St += s_p3[0][w]; At += s_p3[1][w]; Pt += s_p3[2][w]; }
        float sum_p15 = At / (St * sqrtf(St));
        float omega   = (1.0f - sum_p15) / 0.75f;        // alpha*(alpha-1) = 0.75
        g_loss[row] = omega + 2.0f * Pt / St - xt;

        __threadfence();
        int t = atomicAdd(&g_done, 1);
        s_last = (t == NROWS - 1);
    }
    __syncthreads();

    // ================= last block: deterministic mean =======================================
    if (s_last) {
        if (tid == 0) g_done = 0;
        __threadfence();
        float a = 0.f;
        #pragma unroll 4
        for (int i = tid; i < NROWS; i += TA) a += g_loss[i];
        a = warp_sum(a);
        if (lane == 0) s_p3[0][wid] = a;
        __syncthreads();
        if (tid == 0) {
            float tot = 0.f;
            #pragma unroll
            for (int w = 0; w < NWARP; w++) tot += s_p3[0][w];
            out[0] = tot / (float)NROWS;
        }
    }
}

// ============================================================================
extern "C" void kernel_launch(void* const* d_in, const int* in_sizes, int n_in,
                              void* d_out, int out_size)
{
    const float* X      = (const float*)d_in[0];
    const int*   target = (const int*)  d_in[1];
    float*       out    = (float*)d_out;

    fused_kernel<<<NROWS, TA>>>(X, target, out);
}

// round 6
// speedup vs baseline: 1.5267x; 1.0943x over previous
#include <cuda_runtime.h>
#include <cuda_bf16.h>
#include <math_constants.h>

#define D       32000
#define D4      8000
#define NROWS   4096
#define TA      256
#define NWARP   8
#define CHUNK4  1000            // float4s per warp chunk
#define SUBF4   125             // float4s per sub-step
#define NSUB    8
#define WCAP    512             // per-warp coarse-candidate capacity (pow2; exp 267, +15 sigma)
#define NBIS    8
#define NNEWT   4
#define XT      1.5f            // coarse threshold (X scale); valid iff rowmaxX > XT+2 (checked)
#define CHI     0.005590169943749474f   // (1/32000)^0.5

__device__ float g_loss[NROWS];
__device__ int   g_done;        // zero-init; last block resets (graph-replay safe)

__device__ __forceinline__ float warp_sum(float v) {
    #pragma unroll
    for (int o = 16; o; o >>= 1) v += __shfl_xor_sync(0xffffffffu, v, o);
    return v;
}
__device__ __forceinline__ float warp_max(float v) {
    #pragma unroll
    for (int o = 16; o; o >>= 1) v = fmaxf(v, __shfl_xor_sync(0xffffffffu, v, o));
    return v;
}

#define FOR16(OP) OP(c0.x) OP(c0.y) OP(c0.z) OP(c0.w) \
                  OP(c1.x) OP(c1.y) OP(c1.z) OP(c1.w) \
                  OP(c2.x) OP(c2.y) OP(c2.z) OP(c2.w) \
                  OP(c3.x) OP(c3.y) OP(c3.z) OP(c3.w)

__global__ void __launch_bounds__(TA, 5) fused_kernel(const float* __restrict__ X,
                                                      const int*   __restrict__ target,
                                                      float*       __restrict__ out)
{
    __shared__ float s_buf[NWARP][WCAP];     // 16 KB coarse candidates (Xa scale)
    __shared__ float s_F[2][NWARP], s_G[2][NWARP];
    __shared__ float s_p3[3][NWARP];
    __shared__ float s_max[NWARP];
    __shared__ int   s_fb;
    __shared__ int   s_last;

    const int row  = blockIdx.x;
    const int tid  = threadIdx.x;
    const int lane = tid & 31;
    const int wid  = tid >> 5;

    if (tid == 0) s_fb = 0;
    __syncthreads();

    const float4* __restrict__ Xr4 = reinterpret_cast<const float4*>(X + (size_t)row * D);
    const float*  __restrict__ Xr  = X + (size_t)row * D;
    const float4* __restrict__ W4  = Xr4 + wid * CHUNK4;

    float xt = 0.f;
    if (tid == 0) xt = Xr[target[row]];

    // ============ single-pass filter: constant threshold, no max, branch-free writes =======
    const float4 FILL = make_float4(-CUDART_INF_F, -CUDART_INF_F, -CUDART_INF_F, -CUDART_INF_F);
    #define LOADSUB(dst0,dst1,dst2,dst3,sub) do {                        \
        int _b = (sub) * SUBF4;                                          \
        dst0 = W4[_b + lane];                                            \
        dst1 = W4[_b + lane + 32];                                       \
        dst2 = W4[_b + lane + 64];                                       \
        dst3 = (lane + 96 < SUBF4) ? W4[_b + lane + 96] : FILL;          \
    } while (0)

    float4 a0, a1, a2, a3, b0, b1, b2, b3;
    LOADSUB(a0, a1, a2, a3, 0);
    LOADSUB(b0, b1, b2, b3, 1);

    int k = 0;
    #pragma unroll
    for (int sub = 0; sub < NSUB; sub++) {
        float4 c0 = a0, c1 = a1, c2 = a2, c3 = a3;
        a0 = b0; a1 = b1; a2 = b2; a3 = b3;
        if (sub + 2 < NSUB) LOADSUB(b0, b1, b2, b3, sub + 2);

        int ks = 0;
        #define CNT(a) ks += ((a) > XT);
        FOR16(CNT)
        #undef CNT

        int inc = ks;
        #pragma unroll
        for (int o = 1; o < 32; o <<= 1) {
            int n = __shfl_up_sync(0xffffffffu, inc, o);
            if (lane >= o) inc += n;
        }
        int o = k + (inc - ks);
        #define WR(a) { bool p = (a) > XT;                                   \
                        if (p) s_buf[wid][o & (WCAP - 1)] = 0.5f * (a);      \
                        o += p; }
        FOR16(WR)
        #undef WR
        k += __shfl_sync(0xffffffffu, inc, 31);
    }
    #undef LOADSUB

    if (k > WCAP) s_fb = 1;                  // benign race; wrapped buffer never used
    __syncwarp();                            // order all lanes' STS before cross-lane LDS

    // ---- candidate max (the row max always passes the filter when valid) ----
    {
        const int kk = (k < WCAP) ? k : WCAP;
        float cm = -CUDART_INF_F;
        for (int i = lane; i < kk; i += 32) cm = fmaxf(cm, s_buf[wid][i]);
        cm = warp_max(cm);
        if (lane == 0) s_max[wid] = cm;      // Xa scale (0.5*X), -inf if no candidates
    }
    __syncthreads();

    float rmax = s_max[0];
    #pragma unroll
    for (int w = 1; w < NWARP; w++) rmax = fmaxf(rmax, s_max[w]);
    // fallback if coarse threshold was not a provably valid superset filter
    const bool fb = (s_fb != 0) || !(2.0f * rmax - 2.0f > XT + 1e-4f);

    if (fb) {    // rare: recompute exact row max block-wide
        __syncthreads();
        float m = -CUDART_INF_F;
        for (int i = tid; i < D; i += TA) m = fmaxf(m, Xr[i]);
        m = warp_max(m);
        if (lane == 0) s_max[wid] = m;
        __syncthreads();
        float mm = s_max[0];
        #pragma unroll
        for (int w = 1; w < NWARP; w++) mm = fmaxf(mm, s_max[w]);
        rmax = 0.5f * mm;
    }

    // ============ prune to true candidates (Xa > rmax-1) in place ==========================
    int cnt = 0;
    if (!fb) {
        const float tpa = rmax - 1.0f - 5e-6f;   // margin only adds zero-contributing elems
        const int kk = (k < WCAP) ? k : WCAP;
        const int nb = (kk + 31) >> 5;
        for (int j = 0; j < nb; j++) {
            int i = 32 * j + lane;
            float v = (i < kk) ? s_buf[wid][i] : -CUDART_INF_F;
            bool pred = v > tpa;
            unsigned m = __ballot_sync(0xffffffffu, pred);
            if (pred) s_buf[wid][cnt + __popc(m & ((1u << lane) - 1u))] = v;
            cnt += __popc(m);
        }
    }

    // ============ solve: 8 bisection + 4 safeguarded Newton =================================
    const float tau_lo0 = rmax - 1.0f;
    const float tau_hi  = rmax - CHI;
    float tau_lo = tau_lo0;
    float dm = tau_hi - tau_lo;
    float tau_m = tau_lo;
    int pb = 0;

    #pragma unroll 1
    for (int it = 0; it < NBIS + NNEWT; it++) {
        const bool newton = (it >= NBIS);
        float te;
        if (!newton) { dm *= 0.5f; te = tau_lo + dm; }
        else         { te = tau_m; }

        float F = 0.f, G = 0.f;
        if (!fb) {
            #pragma unroll 4
            for (int i = lane; i < cnt; i += 32) {
                float t = fmaxf(s_buf[wid][i] - te, 0.f);
                F = fmaf(t, t, F); G += t;
            }
        } else {
            for (int i = tid; i < D; i += TA) {
                float t = fmaxf(0.5f * Xr[i] - te, 0.f);
                F = fmaf(t, t, F); G += t;
            }
        }
        #pragma unroll
        for (int o = 16; o; o >>= 1) {
            F += __shfl_xor_sync(0xffffffffu, F, o);
            G += __shfl_xor_sync(0xffffffffu, G, o);
        }
        if (lane == 0) { s_F[pb][wid] = F; s_G[pb][wid] = G; }
        __syncthreads();
        float Ft = 0.f, Gt = 0.f;
        #pragma unroll
        for (int w = 0; w < NWARP; w++) { Ft += s_F[pb][w]; Gt += s_G[pb][w]; }
        const float f = Ft - 1.0f;

        if (!newton) {
            if (f >= 0.f) tau_lo = te;        // f(tau_lo) >= 0 invariant
            if (it == NBIS - 1) tau_m = tau_lo;
        } else {
            float tn = te + f / (2.0f * Gt);  // f' = -2G; Newton from left stays left of root
            tau_m = fminf(fmaxf(tn, tau_lo0), tau_hi);
        }
        pb ^= 1;
    }

    // ============ final stats at tau_m ======================================================
    float S = 0.f, A15 = 0.f, PX = 0.f;
    if (!fb) {
        #pragma unroll 4
        for (int i = lane; i < cnt; i += 32) {
            float v = s_buf[wid][i];
            float t = fmaxf(v - tau_m, 0.f);
            float pr = t * t;
            S += pr; A15 = fmaf(pr, t, A15); PX = fmaf(pr, v, PX);
        }
    } else {
        for (int i = tid; i < D; i += TA) {
            float v = 0.5f * Xr[i];
            float t = fmaxf(v - tau_m, 0.f);
            float pr = t * t;
            S += pr; A15 = fmaf(pr, t, A15); PX = fmaf(pr, v, PX);
        }
    }
    S = warp_sum(S); A15 = warp_sum(A15); PX = warp_sum(PX);
    if (lane == 0) { s_p3[0][wid] = S; s_p3[1][wid] = A15; s_p3[2][wid] = PX; }
    __syncthreads();

    if (tid == 0) {
        float St = 0.f, At = 0.f, Pt = 0.f;
        #pragma unroll
        for (int w = 0; w < NWARP; w++) { St += s_p3[0][w]; At += s_p3[1][w]; Pt += s_p3[2][w]; }
        float sum_p15 = At / (St * sqrtf(St));
        float omega   = (1.0f - sum_p15) / 0.75f;       // alpha*(alpha-1) = 0.75
        g_loss[row] = omega + 2.0f * Pt / St - xt;

        __threadfence();
        int t = atomicAdd(&g_done, 1);
        s_last = (t == NROWS - 1);
    }
    __syncthreads();

    // ============ last block: deterministic mean ============================================
    if (s_last) {
        if (tid == 0) g_done = 0;
        __threadfence();
        float a = 0.f;
        #pragma unroll 4
        for (int i = tid; i < NROWS; i += TA) a += g_loss[i];
        a = warp_sum(a);
        if (lane == 0) s_p3[0][wid] = a;
        __syncthreads();
        if (tid == 0) {
            float tot = 0.f;
            #pragma unroll
            for (int w = 0; w < NWARP; w++) tot += s_p3[0][w];
            out[0] = tot / (float)NROWS;
        }
    }
}

// ============================================================================
extern "C" void kernel_launch(void* const* d_in, const int* in_sizes, int n_in,
                              void* d_out, int out_size)
{
    const float* X      = (const float*)d_in[0];
    const int*   target = (const int*)  d_in[1];
    float*       out    = (float*)d_out;

    fused_kernel<<<NROWS, TA>>>(X, target, out);
}